// round 12
// baseline (speedup 1.0000x reference)
#include <cuda_runtime.h>
#include <stdint.h>

#define HW   16384
#define CIN  64
#define COUT 64
#define NGRP 16      // dp4a: input-channel groups of 4
#define XP   20      // IMMA transpose pitch (words)
#define WP   20      // IMMA weight pitch (words)
#define CPP  132     // IMMA raw-C pitch [ch][pos]

__device__ __forceinline__ unsigned pack4(int a, int b, int c, int d) {
    unsigned lo = __byte_perm((unsigned)a, (unsigned)b, 0x0040);
    unsigned hi = __byte_perm((unsigned)c, (unsigned)d, 0x0040);
    return __byte_perm(lo, hi, 0x5410);
}

__device__ __forceinline__ int dp4a_us(unsigned a, int b, int c) {
    int r;
    asm("dp4a.u32.s32 %0, %1, %2, %3;" : "=r"(r) : "r"(a), "r"(b), "r"(c));
    return r;
}

__device__ __forceinline__ void mma_u8s8(int& c0, int& c1, int& c2, int& c3,
                                         unsigned a0, unsigned a1, unsigned a2,
                                         unsigned a3, unsigned b0, unsigned b1) {
    asm("mma.sync.aligned.m16n8k32.row.col.s32.u8.s8.s32 "
        "{%0,%1,%2,%3}, {%4,%5,%6,%7}, {%8,%9}, {%0,%1,%2,%3};"
        : "+r"(c0), "+r"(c1), "+r"(c2), "+r"(c3)
        : "r"(a0), "r"(a1), "r"(a2), "r"(a3), "r"(b0), "r"(b1));
}

__global__ __launch_bounds__(256, 3) void conv_hybrid(
    const int*   __restrict__ x,
    float*       __restrict__ out,
    const int4*  __restrict__ w,
    const float* __restrict__ wscale,
    const int*   __restrict__ wzp,
    const float* __restrict__ bias,
    const float* __restrict__ iscale,
    const float* __restrict__ oscale,
    const int*   __restrict__ izp_p,
    const int*   __restrict__ ozp_p)
{
    // s_big: IMMA = transpose tile then raw-C accumulators;
    //        dp4a = packed weights (first 1024 words)
    __shared__ uint32_t s_big[COUT * CPP];
    __shared__ uint32_t s_w2[COUT * WP];
    __shared__ float4   s_P[COUT];
    __shared__ float    s_sx[128];

    const int tid = threadIdx.x;
    const int bid = blockIdx.x;

    if (bid % 5 == 0) {
        // ================= dp4a path (images 0..15), verbatim R5 ==========
        const int chunk = bid / 5;             // 0..511
        int* s_wd = (int*)s_big;

        if (tid < COUT) {
            const int o = tid;
            int sum = 0;
#pragma unroll
            for (int g = 0; g < NGRP; g++) {
                int4 v = __ldg(w + o * NGRP + g);
                sum += v.x + v.y + v.z + v.w;
                s_wd[g * COUT + o] = (int)pack4(v.x, v.y, v.z, v.w);
            }
            float s   = iscale[0] * wscale[o] / oscale[0];
            float izp = (float)izp_p[0];
            float zw  = (float)wzp[o];
            float C0  = bias[o] / oscale[0]
                      + s * izp * (64.0f * zw - (float)sum)
                      + (float)ozp_p[0];
            s_P[o] = make_float4(s, C0, -s * zw, 0.0f);
        }
        __syncthreads();

        int gp = (chunk * 256 + tid) << 1;     // 2 consecutive positions
        int b  = gp >> 14;
        int hw = gp & (HW - 1);
        const int2* xb = (const int2*)x + (b * (CIN * HW / 2) + (hw >> 1));

        unsigned xw[NGRP][2];
#pragma unroll
        for (int g = 0; g < NGRP; g++) {
            int2 a0 = __ldg(xb + (g * 4 + 0) * (HW / 2));
            int2 a1 = __ldg(xb + (g * 4 + 1) * (HW / 2));
            int2 a2 = __ldg(xb + (g * 4 + 2) * (HW / 2));
            int2 a3 = __ldg(xb + (g * 4 + 3) * (HW / 2));
            xw[g][0] = pack4(a0.x, a1.x, a2.x, a3.x);
            xw[g][1] = pack4(a0.y, a1.y, a2.y, a3.y);
        }

        int sx0 = 0, sx1 = 0;
#pragma unroll
        for (int g = 0; g < NGRP; g++) {
            sx0 = dp4a_us(xw[g][0], 0x01010101, sx0);
            sx1 = dp4a_us(xw[g][1], 0x01010101, sx1);
        }
        float sxf0 = (float)sx0, sxf1 = (float)sx1;

        float2* o2 = (float2*)out;
        const int out_base = b * COUT * (HW / 2) + (hw >> 1);

        for (int q = 0; q < NGRP; q++) {
            int acc[4][2] = {};
#pragma unroll
            for (int g = 0; g < NGRP; g++) {
                int4 w4 = *(const int4*)(s_wd + g * COUT + q * 4);
                acc[0][0] = dp4a_us(xw[g][0], w4.x, acc[0][0]);
                acc[0][1] = dp4a_us(xw[g][1], w4.x, acc[0][1]);
                acc[1][0] = dp4a_us(xw[g][0], w4.y, acc[1][0]);
                acc[1][1] = dp4a_us(xw[g][1], w4.y, acc[1][1]);
                acc[2][0] = dp4a_us(xw[g][0], w4.z, acc[2][0]);
                acc[2][1] = dp4a_us(xw[g][1], w4.z, acc[2][1]);
                acc[3][0] = dp4a_us(xw[g][0], w4.w, acc[3][0]);
                acc[3][1] = dp4a_us(xw[g][1], w4.w, acc[3][1]);
            }
#pragma unroll
            for (int j = 0; j < 4; j++) {
                int o = q * 4 + j;
                float4 P = s_P[o];
                float f0 = fmaf(P.x, (float)acc[j][0], fmaf(P.z, sxf0, P.y));
                float f1 = fmaf(P.x, (float)acc[j][1], fmaf(P.z, sxf1, P.y));
                float r0 = fminf(fmaxf(rintf(f0), 0.0f), 255.0f);
                float r1 = fminf(fmaxf(rintf(f1), 0.0f), 255.0f);
                o2[out_base + o * (HW / 2)] = make_float2(r0, r1);
            }
        }
        return;
    }

    // ================= IMMA path (images 16..31), verbatim R11 =============
    const int T = 2048 + (bid / 5) * 4 + (bid % 5) - 1;   // global tile 2048..4095

    if (tid < COUT) {
        const int o = tid;
        int sum = 0;
#pragma unroll
        for (int i = 0; i < 4; i++) {
            uint32_t wd[4];
#pragma unroll
            for (int j = 0; j < 4; j++) {
                int4 v = __ldg(w + o * 16 + i * 4 + j);
                sum += v.x + v.y + v.z + v.w;
                wd[j] = pack4(v.x, v.y, v.z, v.w);
            }
            *(uint4*)(s_w2 + o * WP + i * 4) = make_uint4(wd[0], wd[1], wd[2], wd[3]);
        }
        float S   = iscale[0] * wscale[o] / oscale[0];
        float izp = (float)__ldg(izp_p);
        float zw  = (float)__ldg(wzp + o);
        float C0  = bias[o] / oscale[0]
                  + S * izp * (64.0f * zw - (float)sum)
                  + (float)__ldg(ozp_p);
        s_P[o] = make_float4(S, C0, -S * zw, 0.0f);
    }

    const int bb  = T >> 7;
    const int hw0 = (T & 127) << 7;
    const int* xb = x + bb * (CIN * HW) + hw0;
#pragma unroll
    for (int it = 0; it < 2; it++) {
        int task = tid + 256 * it;
        int pos  = task & 127;
        int grp  = task >> 7;
        uint32_t wd[4];
#pragma unroll
        for (int j = 0; j < 4; j++) {
            const int* cp = xb + (grp * 16 + j * 4) * HW + pos;
            int v0 = __ldg(cp + 0 * HW);
            int v1 = __ldg(cp + 1 * HW);
            int v2 = __ldg(cp + 2 * HW);
            int v3 = __ldg(cp + 3 * HW);
            wd[j] = pack4(v0, v1, v2, v3);
        }
        *(uint4*)(s_big + pos * XP + grp * 4) = make_uint4(wd[0], wd[1], wd[2], wd[3]);
    }
    __syncthreads();

    const int wid  = tid >> 5;
    const int lane = tid & 31;
    const int g    = lane >> 2;
    const int t4   = lane & 3;
    const int r0   = wid * 16 + g;
    const int r1   = r0 + 8;

    unsigned a[2][4];
#pragma unroll
    for (int kt = 0; kt < 2; kt++) {
        int wb = t4 + 8 * kt;
        a[kt][0] = s_big[r0 * XP + wb];
        a[kt][1] = s_big[r1 * XP + wb];
        a[kt][2] = s_big[r0 * XP + wb + 4];
        a[kt][3] = s_big[r1 * XP + wb + 4];
    }

    int p0 = 0, p1 = 0;
    p0 = dp4a_us(a[0][0], 0x01010101, p0);
    p0 = dp4a_us(a[0][2], 0x01010101, p0);
    p0 = dp4a_us(a[1][0], 0x01010101, p0);
    p0 = dp4a_us(a[1][2], 0x01010101, p0);
    p1 = dp4a_us(a[0][1], 0x01010101, p1);
    p1 = dp4a_us(a[0][3], 0x01010101, p1);
    p1 = dp4a_us(a[1][1], 0x01010101, p1);
    p1 = dp4a_us(a[1][3], 0x01010101, p1);
    p0 += __shfl_xor_sync(0xffffffffu, p0, 1);
    p0 += __shfl_xor_sync(0xffffffffu, p0, 2);
    p1 += __shfl_xor_sync(0xffffffffu, p1, 1);
    p1 += __shfl_xor_sync(0xffffffffu, p1, 2);
    if (t4 == 0) {
        s_sx[r0] = (float)p0;
        s_sx[r1] = (float)p1;
    }
    __syncthreads();

#pragma unroll
    for (int nt = 0; nt < 8; nt++) {
        const uint32_t* wr = s_w2 + (nt * 8 + g) * WP + t4;
        unsigned b00 = wr[0];
        unsigned b01 = wr[4];
        unsigned b10 = wr[8];
        unsigned b11 = wr[12];
        int c0 = 0, c1 = 0, c2 = 0, c3 = 0;
        mma_u8s8(c0, c1, c2, c3, a[0][0], a[0][1], a[0][2], a[0][3], b00, b01);
        mma_u8s8(c0, c1, c2, c3, a[1][0], a[1][1], a[1][2], a[1][3], b10, b11);

        const int ch = nt * 8 + 2 * t4;
        s_big[(ch + 0) * CPP + r0] = (uint32_t)c0;
        s_big[(ch + 1) * CPP + r0] = (uint32_t)c1;
        s_big[(ch + 0) * CPP + r1] = (uint32_t)c2;
        s_big[(ch + 1) * CPP + r1] = (uint32_t)c3;
    }
    __syncthreads();

    const int pos = tid & 127;
    const int cb  = (tid >> 7) * 32;
    const float sxf = s_sx[pos];
    float* const ob = out + bb * (COUT * HW) + hw0 + pos;
#pragma unroll
    for (int j = 0; j < 32; j++) {
        const int ch = cb + j;
        int c = (int)s_big[ch * CPP + pos];
        float4 P = s_P[ch];
        float f = fmaf(P.x, (float)c, fmaf(P.z, sxf, P.y));
        f = fminf(fmaxf(rintf(f), 0.0f), 255.0f);
        ob[ch * HW] = f;
    }
}

extern "C" void kernel_launch(void* const* d_in, const int* in_sizes, int n_in,
                              void* d_out, int out_size) {
    // 0: x_quant (i32)  1: input_scale (f32)  2: input_zero_point (i32)
    // 3: weight_int8 (i32)  4: weight_scale (f32)  5: weight_zero_point (i32)
    // 6: bias_fp32 (f32)  7: output_scale (f32)  8: output_zero_point (i32)
    (void)in_sizes; (void)n_in; (void)out_size;

    // 512 dp4a blocks (images 0..15) + 2048 IMMA blocks (images 16..31),
    // interleaved mod 5 so every SM hosts a mix of both CTA types
    conv_hybrid<<<2560, 256>>>((const int*)d_in[0], (float*)d_out,
                               (const int4*)d_in[3], (const float*)d_in[4],
                               (const int*)d_in[5], (const float*)d_in[6],
                               (const float*)d_in[1], (const float*)d_in[7],
                               (const int*)d_in[2], (const int*)d_in[8]);
}